// round 9
// baseline (speedup 1.0000x reference)
#include <cuda_runtime.h>
#include <math.h>

// Problem constants (fixed by setup_inputs)
#define B_  2
#define T_  8
#define M_  900
#define H_  27
#define W_  27
#define D_  1024
#define PATCH_ 14

#define GRID_  888                         // 148 SMs * 6 blocks/SM = exactly one wave
#define NPAIR_DENOM (B_ * (T_ - 1) * M_)   // 12600, mean denominator

__device__ float        g_partials[GRID_];
__device__ unsigned int g_done = 0;   // reset by the last block each launch

// L1 over 4 dims: abs folds into FADD source modifiers
__device__ __forceinline__ float l1_4(const float4& a, const float4& b)
{
    float d0 = a.x - b.x, d1 = a.y - b.y, d2 = a.z - b.z, d3 = a.w - b.w;
    return (fabsf(d0) + fabsf(d1)) + (fabsf(d2) + fabsf(d3));
}

__global__ __launch_bounds__(256, 6)      // 42-reg budget -> 6 blocks/SM
void gather_l1_onewave_kernel(const float* __restrict__ features,
                              const float* __restrict__ tracks,
                              const int* __restrict__ vis,   // bool stored as int32
                              float* __restrict__ out)
{
    const int tid  = threadIdx.x;         // 256 threads = 1024 floats / 4
    const int lane = tid & 31;
    const int wid  = tid >> 5;

    float acc = 0.0f;

    // Blocks 0..11 handle two tracks (m, m+888); the rest handle one.
    for (int m = blockIdx.x; m < M_; m += GRID_) {
        // Lanes 0..15: lane<8 -> (b=0, t=lane); lane>=8 -> (b=1, t=lane-8).
        int my_nn = 0, my_vis = 0;
        if (lane < 2 * T_) {
            const int bb = lane >> 3;
            const int t  = lane & 7;
            const float2 tr = *(const float2*)(tracks
                + (unsigned)(((bb * T_ + t) * M_ + m) * 2));
            // nearest patch center c_j = 14j+7 -> j = clamp(floor(x/14), 0, 26)
            int j = (int)floorf(tr.x * (1.0f / PATCH_));
            int i = (int)floorf(tr.y * (1.0f / PATCH_));
            j = min(W_ - 1, max(0, j));
            i = min(H_ - 1, max(0, i));
            my_nn  = i * W_ + j;
            my_vis = vis[(unsigned)((bb * T_ + t) * M_ + m)];
        }

#pragma unroll
        for (int bb = 0; bb < B_; bb++) {
            int   nn[T_];
            float fv[T_];
#pragma unroll
            for (int t = 0; t < T_; t++) {
                nn[t] = __shfl_sync(0xffffffffu, my_nn, bb * T_ + t);
                fv[t] = (float)__shfl_sync(0xffffffffu, my_vis, bb * T_ + t);
            }

            // Gather 8 rows; 8 independent LDG.128 per thread, 32-bit offsets.
            float4 pf[T_];
#pragma unroll
            for (int t = 0; t < T_; t++) {
                unsigned off = ((unsigned)((bb * T_ + t) * (H_ * W_) + nn[t]) << 10)
                             + ((unsigned)tid << 2);
                pf[t] = *(const float4*)(features + off);
            }

            // 13 distinct pairs; pair (0,1) serves both consec and ref terms.
            float l01 = l1_4(pf[0], pf[1]);
            float m01 = fv[0] * fv[1];
            float acc_c = m01 * l01;
            float acc_r = m01 * l01;
#pragma unroll
            for (int t = 1; t < T_ - 1; t++) {
                acc_c = fmaf(fv[t] * fv[t + 1], l1_4(pf[t], pf[t + 1]), acc_c);
                acc_r = fmaf(fv[0] * fv[t + 1], l1_4(pf[0], pf[t + 1]), acc_r);
            }
            acc += acc_c + acc_r;         // fixed order -> deterministic
        }
    }

    // --- Block reduction: warp shuffle, then 8 warp sums via shared
#pragma unroll
    for (int o = 16; o > 0; o >>= 1)
        acc += __shfl_down_sync(0xffffffffu, acc, o);

    __shared__ float s_warp[8];
    if (lane == 0) s_warp[wid] = acc;
    __syncthreads();

    __shared__ bool s_is_last;
    if (tid == 0) {
        float s = 0.0f;
#pragma unroll
        for (int w = 0; w < 8; w++) s += s_warp[w];
        g_partials[blockIdx.x] = s;
        __threadfence();
        unsigned int prev = atomicAdd(&g_done, 1u);
        s_is_last = (prev == GRID_ - 1);
    }
    __syncthreads();

    // --- Last block reduces all partials (fixed order -> deterministic)
    if (s_is_last) {
        double dacc = 0.0;
#pragma unroll
        for (int k = 0; k < (GRID_ + 255) / 256; k++) {
            int i = k * 256 + tid;
            if (i < GRID_) dacc += (double)g_partials[i];
        }
#pragma unroll
        for (int o = 16; o > 0; o >>= 1)
            dacc += __shfl_down_sync(0xffffffffu, dacc, o);

        __shared__ double s_dwarp[8];
        if (lane == 0) s_dwarp[wid] = dacc;
        __syncthreads();
        if (tid == 0) {
            double s = 0.0;
#pragma unroll
            for (int w = 0; w < 8; w++) s += s_dwarp[w];
            out[0] = (float)(0.01 * s / (double)NPAIR_DENOM);
            g_done = 0;                   // reset for next graph replay
        }
    }
}

extern "C" void kernel_launch(void* const* d_in, const int* in_sizes, int n_in,
                              void* d_out, int out_size)
{
    const float* features = (const float*)d_in[0];  // [B*T, H*W, D] f32
    const float* tracks   = (const float*)d_in[1];  // [B, T, M, 2]  f32
    const int*   vis      = (const int*)d_in[2];    // [B, T, M]     bool->int32
    float*       out      = (float*)d_out;

    gather_l1_onewave_kernel<<<GRID_, 256>>>(features, tracks, vis, out);
}

// round 10
// speedup vs baseline: 1.0025x; 1.0025x over previous
#include <cuda_runtime.h>
#include <math.h>

// Problem constants (fixed by setup_inputs)
#define B_  2
#define T_  8
#define M_  900
#define H_  27
#define W_  27
#define D_  1024
#define PATCH_ 14

#define NBLK   M_                          // 900 blocks, all resident in ONE wave @ occ7
#define NPAIR_DENOM (B_ * (T_ - 1) * M_)   // 12600, mean denominator

__device__ float        g_partials[NBLK];
__device__ unsigned int g_done = 0;   // reset by the last block each launch

// L1 over 4 dims: abs folds into FADD source modifiers
__device__ __forceinline__ float l1_4(const float4& a, const float4& b)
{
    float d0 = a.x - b.x, d1 = a.y - b.y, d2 = a.z - b.z, d3 = a.w - b.w;
    return (fabsf(d0) + fabsf(d1)) + (fabsf(d2) + fabsf(d3));
}

__global__ __launch_bounds__(256, 7)      // 36-reg budget -> 7 blocks/SM, 1036 slots >= 900
void gather_l1_onewave_kernel(const float* __restrict__ features,
                              const float* __restrict__ tracks,
                              const int* __restrict__ vis,   // bool stored as int32
                              float* __restrict__ out)
{
    const int m    = blockIdx.x;          // 0..899
    const int tid  = threadIdx.x;         // 256 threads = 1024 floats / 4
    const int lane = tid & 31;
    const int wid  = tid >> 5;

    // --- Lanes 0..15: lane<8 -> (b=0, t=lane); lane>=8 -> (b=1, t=lane-8).
    // Each lane resolves the FULL row byte-offset base and visibility for its frame.
    unsigned my_off = 0;
    int      my_vis = 0;
    if (lane < 2 * T_) {
        const int bb = lane >> 3;
        const int t  = lane & 7;
        const float2 tr = *(const float2*)(tracks
            + (unsigned)(((bb * T_ + t) * M_ + m) * 2));
        // nearest patch center c_j = 14j+7 -> j = clamp(floor(x/14), 0, 26)
        int j = (int)floorf(tr.x * (1.0f / PATCH_));
        int i = (int)floorf(tr.y * (1.0f / PATCH_));
        j = min(W_ - 1, max(0, j));
        i = min(H_ - 1, max(0, i));
        my_off = (unsigned)((bb * T_ + t) * (H_ * W_) + i * W_ + j) << 10;  // element offset of row start
        my_vis = vis[(unsigned)((bb * T_ + t) * M_ + m)];
    }
    const unsigned tcol = (unsigned)tid << 2;   // this thread's float4 lane within a row

    float acc = 0.0f;

#pragma unroll
    for (int bb = 0; bb < B_; bb++) {
        const int sb = bb * T_;
        // shuffle row offsets / visibility at point of use (no register arrays)
#define ROFF(t) (__shfl_sync(0xffffffffu, my_off, sb + (t)) + tcol)
#define FVI(t)  ((float)__shfl_sync(0xffffffffu, my_vis, sb + (t)))

        // Ring-of-3 stream: live set = p0, r1, r2, r3 (16 regs)
        float4 p0 = *(const float4*)(features + ROFF(0));
        float4 r1 = *(const float4*)(features + ROFF(1));
        float4 r2 = *(const float4*)(features + ROFF(2));
        float4 r3 = *(const float4*)(features + ROFF(3));

        float fv0 = FVI(0);
        float fvc = FVI(1);
        float l01 = l1_4(p0, r1);
        float m01 = fv0 * fvc;
        float ac = m01 * l01;             // consec pair (0,1)
        float ar = m01 * l01;             // ref pair (0,1) — same pair

        // t=1: pairs (1,2) and (0,2); r1 (row1) dies -> refill with row4
        float fvn = FVI(2);
        ac = fmaf(fvc * fvn, l1_4(r1, r2), ac);
        ar = fmaf(fv0 * fvn, l1_4(p0, r2), ar);
        r1 = *(const float4*)(features + ROFF(4));
        fvc = fvn;

        // t=2: pairs (2,3) and (0,3); r2 (row2) dies -> refill with row5
        fvn = FVI(3);
        ac = fmaf(fvc * fvn, l1_4(r2, r3), ac);
        ar = fmaf(fv0 * fvn, l1_4(p0, r3), ar);
        r2 = *(const float4*)(features + ROFF(5));
        fvc = fvn;

        // t=3: pairs (3,4) and (0,4); rows: r3=row3, r1=row4; r3 dies -> row6
        fvn = FVI(4);
        ac = fmaf(fvc * fvn, l1_4(r3, r1), ac);
        ar = fmaf(fv0 * fvn, l1_4(p0, r1), ar);
        r3 = *(const float4*)(features + ROFF(6));
        fvc = fvn;

        // t=4: pairs (4,5) and (0,5); rows: r1=row4, r2=row5; r1 dies -> row7
        fvn = FVI(5);
        ac = fmaf(fvc * fvn, l1_4(r1, r2), ac);
        ar = fmaf(fv0 * fvn, l1_4(p0, r2), ar);
        r1 = *(const float4*)(features + ROFF(7));
        fvc = fvn;

        // t=5: pairs (5,6) and (0,6); rows: r2=row5, r3=row6
        fvn = FVI(6);
        ac = fmaf(fvc * fvn, l1_4(r2, r3), ac);
        ar = fmaf(fv0 * fvn, l1_4(p0, r3), ar);
        fvc = fvn;

        // t=6: pairs (6,7) and (0,7); rows: r3=row6, r1=row7
        fvn = FVI(7);
        ac = fmaf(fvc * fvn, l1_4(r3, r1), ac);
        ar = fmaf(fv0 * fvn, l1_4(p0, r1), ar);

        acc += ac + ar;                   // fixed order -> deterministic
#undef ROFF
#undef FVI
    }

    // --- Block reduction: warp shuffle, then 8 warp sums via shared
#pragma unroll
    for (int o = 16; o > 0; o >>= 1)
        acc += __shfl_down_sync(0xffffffffu, acc, o);

    __shared__ float s_warp[8];
    if (lane == 0) s_warp[wid] = acc;
    __syncthreads();

    __shared__ bool s_is_last;
    if (tid == 0) {
        float s = 0.0f;
#pragma unroll
        for (int w = 0; w < 8; w++) s += s_warp[w];
        g_partials[m] = s;
        __threadfence();
        unsigned int prev = atomicAdd(&g_done, 1u);
        s_is_last = (prev == NBLK - 1);
    }
    __syncthreads();

    // --- Last block reduces all partials (fixed order -> deterministic)
    if (s_is_last) {
        double dacc = 0.0;
#pragma unroll
        for (int k = 0; k < (NBLK + 255) / 256; k++) {
            int i = k * 256 + tid;
            if (i < NBLK) dacc += (double)g_partials[i];
        }
#pragma unroll
        for (int o = 16; o > 0; o >>= 1)
            dacc += __shfl_down_sync(0xffffffffu, dacc, o);

        __shared__ double s_dwarp[8];
        if (lane == 0) s_dwarp[wid] = dacc;
        __syncthreads();
        if (tid == 0) {
            double s = 0.0;
#pragma unroll
            for (int w = 0; w < 8; w++) s += s_dwarp[w];
            out[0] = (float)(0.01 * s / (double)NPAIR_DENOM);
            g_done = 0;                   // reset for next graph replay
        }
    }
}

extern "C" void kernel_launch(void* const* d_in, const int* in_sizes, int n_in,
                              void* d_out, int out_size)
{
    const float* features = (const float*)d_in[0];  // [B*T, H*W, D] f32
    const float* tracks   = (const float*)d_in[1];  // [B, T, M, 2]  f32
    const int*   vis      = (const int*)d_in[2];    // [B, T, M]     bool->int32
    float*       out      = (float*)d_out;

    gather_l1_onewave_kernel<<<NBLK, 256>>>(features, tracks, vis, out);
}